// round 2
// baseline (speedup 1.0000x reference)
#include <cuda_runtime.h>
#include <float.h>
#include <stdint.h>

#define BATCH 8
#define NPT   2048
#define KNB   16
#define BN    (BATCH*NPT)   // 16384

// ---------------- scratch (__device__ globals: allocation-free) ----------------
__device__ float g_D[(size_t)BATCH*NPT*NPT];   // 134MB distance matrix (reused 3x)
__device__ float g_sq[BN];
__device__ int   g_idx[BN*KNB];
__device__ float g_x2[BN*32];
__device__ float g_x3[BN*128];
__device__ float g_A [BN*256];                 // factored layer-1: ctr-projection (+bias)
__device__ float g_Bf[BN*256];                 // factored layer-1: nbr-projection
__device__ float g_x4[BN*128];
__device__ float g_x5p[BATCH*16*128];

__device__ __forceinline__ float lrelu(float v) { return v >= 0.f ? v : 0.01f*v; }

// ---------------- squared norms (warp per point) ----------------
__global__ void sq_kernel(const float* __restrict__ X, int C) {
    int gw   = (blockIdx.x*blockDim.x + threadIdx.x) >> 5;
    int lane = threadIdx.x & 31;
    if (gw >= BN) return;
    const float* r = X + (size_t)gw*C;
    float acc = 0.f;
    for (int c = lane; c < C; c += 32) { float v = r[c]; acc += v*v; }
    #pragma unroll
    for (int o = 16; o; o >>= 1) acc += __shfl_xor_sync(0xffffffffu, acc, o);
    if (lane == 0) g_sq[gw] = acc;
}

// ---------------- pairwise distance: D = sq_i + sq_j - 2*dot ----------------
// 64x64 tile, 256 threads, 4x4 register microtile (16 FMA per 8 LDS)
template<int C>
__global__ __launch_bounds__(256) void dist_kernel(const float* __restrict__ X) {
    constexpr int CT = (C < 32) ? C : 32;
    __shared__ float As[CT][65];   // +1 pad kills store conflicts
    __shared__ float Bs[CT][65];
    int b  = blockIdx.z;
    int i0 = blockIdx.y * 64, j0 = blockIdx.x * 64;
    const float* Xb = X + (size_t)b*NPT*C;
    int t  = threadIdx.x;
    int tx = t & 15, ty = t >> 4;
    float acc[4][4] = {};
    for (int c0 = 0; c0 < C; c0 += CT) {
        __syncthreads();
        for (int e = t; e < 64*CT; e += 256) {
            int r = e / CT, c = e % CT;
            As[c][r] = Xb[(size_t)(i0 + r)*C + c0 + c];
            Bs[c][r] = Xb[(size_t)(j0 + r)*C + c0 + c];
        }
        __syncthreads();
        #pragma unroll
        for (int c = 0; c < CT; c++) {
            float av[4], bv[4];
            #pragma unroll
            for (int u = 0; u < 4; u++) { av[u] = As[c][ty*4+u]; bv[u] = Bs[c][tx*4+u]; }
            #pragma unroll
            for (int ii = 0; ii < 4; ii++)
                #pragma unroll
                for (int jj = 0; jj < 4; jj++)
                    acc[ii][jj] += av[ii]*bv[jj];
        }
    }
    const float* sqb = g_sq + b*NPT;
    float* Db = g_D + (size_t)b*NPT*NPT;
    int j = j0 + tx*4;
    float s0 = sqb[j+0], s1 = sqb[j+1], s2 = sqb[j+2], s3 = sqb[j+3];
    #pragma unroll
    for (int ii = 0; ii < 4; ii++) {
        int i = i0 + ty*4 + ii;
        float si = sqb[i];
        float4 o;
        o.x = si + s0 - 2.f*acc[ii][0];
        o.y = si + s1 - 2.f*acc[ii][1];
        o.z = si + s2 - 2.f*acc[ii][2];
        o.w = si + s3 - 2.f*acc[ii][3];
        *(float4*)(Db + (size_t)i*NPT + j) = o;
    }
}

// ---------------- top-16 (block per row, iterative argmin in smem) ----------------
#define PHYS(s) ((s) + ((s) >> 5))    // pad: stride-128 scan -> conflict-free banks
__global__ __launch_bounds__(128) void topk_kernel() {
    __shared__ float sd[NPT + 64];
    __shared__ float rbest[4];
    __shared__ int   ribest[4];
    int row = blockIdx.x;
    const float* Dr = g_D + (size_t)row * NPT;
    int t = threadIdx.x;
    for (int s = t; s < NPT; s += 128) sd[PHYS(s)] = Dr[s];
    __syncthreads();
    for (int it = 0; it < KNB; it++) {
        float best = FLT_MAX; int bi = NPT;
        for (int s = t; s < NPT; s += 128) {
            float v = sd[PHYS(s)];
            if (v < best) { best = v; bi = s; }     // strict < keeps lowest index in-thread
        }
        #pragma unroll
        for (int o = 16; o; o >>= 1) {
            float ov = __shfl_down_sync(0xffffffffu, best, o);
            int   oi = __shfl_down_sync(0xffffffffu, bi, o);
            if (ov < best || (ov == best && oi < bi)) { best = ov; bi = oi; }
        }
        if ((t & 31) == 0) { rbest[t>>5] = best; ribest[t>>5] = bi; }
        __syncthreads();
        if (t == 0) {
            #pragma unroll
            for (int w = 1; w < 4; w++)
                if (rbest[w] < best || (rbest[w] == best && ribest[w] < bi)) { best = rbest[w]; bi = ribest[w]; }
            g_idx[row*KNB + it] = bi;
            sd[PHYS(bi)] = FLT_MAX;
        }
        __syncthreads();
    }
}

// ---------------- block 1: edge MLP 6->16->64->32, sum over K ----------------
// thread per (point, k); 8 points / block; weights in smem (broadcast reads)
__global__ __launch_bounds__(128) void mlp1_kernel(
        const float* __restrict__ x,
        const float* __restrict__ w1, const float* __restrict__ b1,
        const float* __restrict__ w2, const float* __restrict__ b2,
        const float* __restrict__ w3, const float* __restrict__ b3) {
    __shared__ float s1[96], sb1[16], s2[1024], sb2[64], s3[2048], sb3[32];
    int t = threadIdx.x;
    if (t < 96) s1[t] = w1[t];
    if (t < 16) sb1[t] = b1[t];
    for (int e = t; e < 1024; e += 128) s2[e] = w2[e];
    if (t < 64) sb2[t] = b2[t];
    for (int e = t; e < 2048; e += 128) s3[e] = w3[e];
    if (t < 32) sb3[t] = b3[t];
    __syncthreads();
    int k = t & 15, lp = t >> 4;
    int p = blockIdx.x * 8 + lp;
    int b = p >> 11;
    int j = g_idx[p*KNB + k];
    float in[6];
    const float* xc = x + (size_t)p*3;
    const float* xn = x + (size_t)(b*NPT + j)*3;
    in[0]=xc[0]; in[1]=xc[1]; in[2]=xc[2];
    in[3]=xn[0]; in[4]=xn[1]; in[5]=xn[2];
    float h16[16];
    #pragma unroll
    for (int o = 0; o < 16; o++) {
        float a = sb1[o];
        #pragma unroll
        for (int c = 0; c < 6; c++) a += s1[c*16+o]*in[c];
        h16[o] = lrelu(a);
    }
    float h64[64];
    #pragma unroll
    for (int o = 0; o < 64; o++) {
        float a = sb2[o];
        #pragma unroll
        for (int c = 0; c < 16; c++) a += s2[c*64+o]*h16[c];
        h64[o] = lrelu(a);
    }
    float h32[32];
    #pragma unroll
    for (int o = 0; o < 32; o++) {
        float a = sb3[o];
        #pragma unroll
        for (int c = 0; c < 64; c++) a += s3[c*32+o]*h64[c];
        h32[o] = lrelu(a);
    }
    // sum over k within 16-lane groups
    #pragma unroll
    for (int c = 0; c < 32; c++) {
        #pragma unroll
        for (int o = 8; o; o >>= 1) h32[c] += __shfl_xor_sync(0xffffffffu, h32[c], o);
    }
    if (k == 0) {
        float* outp = g_x2 + (size_t)p*32;
        #pragma unroll
        for (int c = 0; c < 32; c++) outp[c] = h32[c];
    }
}

// ---------------- factored layer-1 projections: A = X@W[0:CIN]+b, Bf = X@W[CIN:2CIN] ----------------
template<int CIN, int COUT>
__global__ __launch_bounds__(256) void proj_kernel(
        const float* __restrict__ X, const float* __restrict__ W,
        const float* __restrict__ bias) {
    constexpr int OG = COUT/4;
    constexpr int R  = 256/OG;
    __shared__ float sin[R][CIN];
    int t = threadIdx.x;
    int p0 = blockIdx.x * R;
    for (int e = t; e < R*CIN; e += 256) sin[e / CIN][e % CIN] = X[(size_t)p0*CIN + e];
    __syncthreads();
    int og = t % OG, r = t / OG;
    float4 aa = {0,0,0,0}, bb = {0,0,0,0};
    #pragma unroll 4
    for (int c = 0; c < CIN; c++) {
        float v = sin[r][c];
        float4 wa = *(const float4*)(W + (size_t)c*COUT + og*4);
        float4 wb = *(const float4*)(W + (size_t)(CIN + c)*COUT + og*4);
        aa.x += wa.x*v; aa.y += wa.y*v; aa.z += wa.z*v; aa.w += wa.w*v;
        bb.x += wb.x*v; bb.y += wb.y*v; bb.z += wb.z*v; bb.w += wb.w*v;
    }
    float4 b4 = *(const float4*)(bias + og*4);
    aa.x += b4.x; aa.y += b4.y; aa.z += b4.z; aa.w += b4.w;
    *(float4*)(g_A  + (size_t)(p0 + r)*COUT + og*4) = aa;
    *(float4*)(g_Bf + (size_t)(p0 + r)*COUT + og*4) = bb;
}

// ---------------- block 2 heavy kernel: h1[k]=lrelu(A[n]+Bf[j_k]); x3=sum_k lrelu(h1@W2+b2) ----------------
#define MLP2_SMEM ((32768 + 128 + 256 + 4096 + 1024)*4 + KNB*4)
__global__ __launch_bounds__(256) void mlp2_kernel(
        const float* __restrict__ W2, const float* __restrict__ b2) {
    extern __shared__ float sm[];
    float* W2s = sm;                  // 256*128
    float* b2s = W2s + 32768;         // 128
    float* a_s = b2s + 128;           // 256
    float* h1s = a_s + 256;           // 16*256
    float* red = h1s + 4096;          // 8*128
    int*  idxs = (int*)(red + 1024);  // 16
    int t = threadIdx.x;
    for (int e = t; e < 8192; e += 256) ((float4*)W2s)[e] = ((const float4*)W2)[e];
    if (t < 128) b2s[t] = b2[t];
    for (int pp = 0; pp < 8; pp++) {
        int p = blockIdx.x*8 + pp;
        int b = p >> 11;
        __syncthreads();                      // weights (1st iter) / smem reuse (later)
        if (t < KNB) idxs[t] = g_idx[p*KNB + t];
        a_s[t] = g_A[(size_t)p*256 + t];
        __syncthreads();
        {   // layer 1 (factored): gather + add + lrelu
            int k = t >> 4, q = t & 15;
            const float* Br = g_Bf + (size_t)(b*NPT + idxs[k])*256;
            #pragma unroll
            for (int e = 0; e < 4; e++) {
                int c = q*16 + e*4;
                float4 bv = *(const float4*)(Br + c);
                float4 av = *(const float4*)(a_s + c);
                float4 h;
                h.x = lrelu(av.x + bv.x); h.y = lrelu(av.y + bv.y);
                h.z = lrelu(av.z + bv.z); h.w = lrelu(av.w + bv.w);
                *(float4*)(h1s + k*256 + c) = h;
            }
        }
        __syncthreads();
        {   // layer 2: 256 -> 128 per k, lrelu, partial-sum over 2 k's per thread
            int cg = t & 31, kg = t >> 5;
            const float* h0 = h1s + (kg*2)*256;
            const float* h1 = h0 + 256;
            float4 a0 = {0,0,0,0}, a1 = {0,0,0,0};
            #pragma unroll 4
            for (int c = 0; c < 256; c++) {
                float4 w = *(const float4*)(W2s + c*128 + cg*4);
                float v0 = h0[c], v1 = h1[c];
                a0.x += w.x*v0; a0.y += w.y*v0; a0.z += w.z*v0; a0.w += w.w*v0;
                a1.x += w.x*v1; a1.y += w.y*v1; a1.z += w.z*v1; a1.w += w.w*v1;
            }
            float4 bb = *(const float4*)(b2s + cg*4);
            float4 s;
            s.x = lrelu(a0.x+bb.x) + lrelu(a1.x+bb.x);
            s.y = lrelu(a0.y+bb.y) + lrelu(a1.y+bb.y);
            s.z = lrelu(a0.z+bb.z) + lrelu(a1.z+bb.z);
            s.w = lrelu(a0.w+bb.w) + lrelu(a1.w+bb.w);
            *(float4*)(red + kg*128 + cg*4) = s;
        }
        __syncthreads();
        if (t < 128) {
            float sum = 0.f;
            #pragma unroll
            for (int kg = 0; kg < 8; kg++) sum += red[kg*128 + t];
            g_x3[(size_t)p*128 + t] = sum;
        }
    }
}

// ---------------- block 3 (fully factored): x4 = sum_k lrelu(A3[n] + B3[j_k]) ----------------
__global__ __launch_bounds__(128) void block3_kernel() {
    __shared__ int idxs[KNB];
    int p = blockIdx.x, t = threadIdx.x;
    int b = p >> 11;
    if (t < KNB) idxs[t] = g_idx[p*KNB + t];
    __syncthreads();
    float a = g_A[(size_t)p*128 + t];
    float acc = 0.f;
    #pragma unroll
    for (int k = 0; k < KNB; k++)
        acc += lrelu(a + g_Bf[(size_t)(b*NPT + idxs[k])*128 + t]);
    g_x4[(size_t)p*128 + t] = acc;
}

// ---------------- global max pool (partials) ----------------
__global__ __launch_bounds__(128) void maxpool_kernel() {
    int b = blockIdx.x, seg = blockIdx.y, t = threadIdx.x;
    const float* base = g_x4 + ((size_t)b*NPT + seg*128)*128 + t;
    float m = -FLT_MAX;
    #pragma unroll 8
    for (int r = 0; r < 128; r++) m = fmaxf(m, base[(size_t)r*128]);
    g_x5p[(b*16 + seg)*128 + t] = m;
}

// ---------------- final: reduce pool + fc1 + fc2 + fc3 ----------------
__global__ __launch_bounds__(128) void final_kernel(
        const float* __restrict__ fc1w, const float* __restrict__ fc1b,
        const float* __restrict__ fc2w, const float* __restrict__ fc2b,
        const float* __restrict__ fc3w, const float* __restrict__ fc3b,
        float* __restrict__ out) {
    __shared__ float s5[128], s6[128], s7[128];
    int b = blockIdx.x, t = threadIdx.x;
    float m = -FLT_MAX;
    #pragma unroll
    for (int s = 0; s < 16; s++) m = fmaxf(m, g_x5p[(b*16+s)*128 + t]);
    s5[t] = m;
    __syncthreads();
    float a = fc1b[t];
    #pragma unroll 8
    for (int c = 0; c < 128; c++) a += fc1w[c*128+t]*s5[c];
    s6[t] = lrelu(a);
    __syncthreads();
    a = fc2b[t];
    #pragma unroll 8
    for (int c = 0; c < 128; c++) a += fc2w[c*128+t]*s6[c];
    s7[t] = lrelu(a);
    __syncthreads();
    float* ob = out + (size_t)b*6144;
    for (int o0 = 0; o0 < 6144; o0 += 512) {
        float acc[4];
        #pragma unroll
        for (int u = 0; u < 4; u++) acc[u] = fc3b[o0 + u*128 + t];
        #pragma unroll 4
        for (int c = 0; c < 128; c++) {
            float v = s7[c];
            const float* wr = fc3w + (size_t)c*6144 + o0 + t;
            #pragma unroll
            for (int u = 0; u < 4; u++) acc[u] += wr[u*128]*v;
        }
        #pragma unroll
        for (int u = 0; u < 4; u++) ob[o0 + u*128 + t] = acc[u];
    }
}

// ---------------- host ----------------
extern "C" void kernel_launch(void* const* d_in, const int* in_sizes, int n_in,
                              void* d_out, int out_size) {
    const float* x    = (const float*)d_in[0];
    const float* h1w1 = (const float*)d_in[1];
    const float* h1b1 = (const float*)d_in[2];
    const float* h1w2 = (const float*)d_in[3];
    const float* h1b2 = (const float*)d_in[4];
    const float* h1w3 = (const float*)d_in[5];
    const float* h1b3 = (const float*)d_in[6];
    const float* h2w1 = (const float*)d_in[7];
    const float* h2b1 = (const float*)d_in[8];
    const float* h2w2 = (const float*)d_in[9];
    const float* h2b2 = (const float*)d_in[10];
    const float* h3w1 = (const float*)d_in[11];
    const float* h3b1 = (const float*)d_in[12];
    const float* fc1w = (const float*)d_in[13];
    const float* fc1b = (const float*)d_in[14];
    const float* fc2w = (const float*)d_in[15];
    const float* fc2b = (const float*)d_in[16];
    const float* fc3w = (const float*)d_in[17];
    const float* fc3b = (const float*)d_in[18];
    float* out = (float*)d_out;

    cudaFuncSetAttribute(mlp2_kernel, cudaFuncAttributeMaxDynamicSharedMemorySize, MLP2_SMEM);

    dim3 dgrid(32, 32, BATCH);

    // ---- stage 1 (C=3) ----
    sq_kernel<<<2048, 256>>>(x, 3);
    dist_kernel<3><<<dgrid, 256>>>(x);
    topk_kernel<<<BN, 128>>>();
    mlp1_kernel<<<BN/8, 128>>>(x, h1w1, h1b1, h1w2, h1b2, h1w3, h1b3);

    // ---- stage 2 (C=32) ----
    void* p2; cudaGetSymbolAddress(&p2, g_x2);
    void* p3; cudaGetSymbolAddress(&p3, g_x3);
    sq_kernel<<<2048, 256>>>((const float*)p2, 32);
    dist_kernel<32><<<dgrid, 256>>>((const float*)p2);
    topk_kernel<<<BN, 128>>>();
    proj_kernel<32, 256><<<BN/4, 256>>>((const float*)p2, h2w1, h2b1);
    mlp2_kernel<<<BN/8, 256, MLP2_SMEM>>>(h2w2, h2b2);

    // ---- stage 3 (C=128) ----
    sq_kernel<<<2048, 256>>>((const float*)p3, 128);
    dist_kernel<128><<<dgrid, 256>>>((const float*)p3);
    topk_kernel<<<BN, 128>>>();
    proj_kernel<128, 128><<<BN/8, 256>>>((const float*)p3, h3w1, h3b1);
    block3_kernel<<<BN, 128>>>();

    // ---- head ----
    maxpool_kernel<<<dim3(BATCH, 16), 128>>>();
    final_kernel<<<BATCH, 128>>>(fc1w, fc1b, fc2w, fc2b, fc3w, fc3b, out);
}